// round 9
// baseline (speedup 1.0000x reference)
#include <cuda_runtime.h>
#include <cuda_bf16.h>
#include <cstdint>
#include <math.h>

#define T_TOK 16384
#define N_EXP 256
#define HID   4096

#define BM   128
#define KC   32                 // fp32 k-elements per chunk
#define NCH  (HID / KC)         // 128 chunks
#define ROWB 80                 // padded smem row stride (64B data + 16B pad)

#define A_TERM_BYTES (128 * ROWB)   // 10240
#define W_TERM_BYTES (256 * ROWB)   // 20480
#define W_BASE (2 * A_TERM_BYTES)                        // 20480
#define BUF_BYTES (2 * A_TERM_BYTES + 2 * W_TERM_BYTES)  // 61440
#define SMEM_TOTAL (2 * BUF_BYTES)                       // 122880

#define DELTA 1e-4f

__device__ float g_logits[(size_t)T_TOK * N_EXP];
__device__ float g_small[(size_t)T_TOK * 16];
__device__ int   g_flag_count;
__device__ int   g_flag_list[T_TOK];

// ---------------- helpers ----------------
__device__ __forceinline__ uint32_t smem_u32(const void* p) {
    uint32_t a;
    asm("{ .reg .u64 t; cvta.to.shared.u64 t, %1; cvt.u32.u64 %0, t; }" : "=r"(a) : "l"(p));
    return a;
}

// split pair (lo,hi) of fp32 into bf16 term0 (c0 packed) and term1 (c1 packed)
__device__ __forceinline__ void cvt_split(float lo, float hi, uint32_t& c0, uint32_t& c1) {
    asm("cvt.rn.bf16x2.f32 %0, %1, %2;" : "=r"(c0) : "f"(hi), "f"(lo));
    float rlo = lo - __uint_as_float(c0 << 16);
    float rhi = hi - __uint_as_float(c0 & 0xffff0000u);
    asm("cvt.rn.bf16x2.f32 %0, %1, %2;" : "=r"(c1) : "f"(rhi), "f"(rlo));
}

// 8 fp32 -> 16B term0 + 16B term1, stored as STS.128
__device__ __forceinline__ void cvt_store8(float4 v0, float4 v1, uint32_t s0, uint32_t s1) {
    uint32_t a0, a1, b0, b1, c0, c1, d0, d1;
    cvt_split(v0.x, v0.y, a0, a1);
    cvt_split(v0.z, v0.w, b0, b1);
    cvt_split(v1.x, v1.y, c0, c1);
    cvt_split(v1.z, v1.w, d0, d1);
    asm volatile("st.shared.v4.b32 [%0], {%1,%2,%3,%4};" :: "r"(s0), "r"(a0), "r"(b0), "r"(c0), "r"(d0));
    asm volatile("st.shared.v4.b32 [%0], {%1,%2,%3,%4};" :: "r"(s1), "r"(a1), "r"(b1), "r"(c1), "r"(d1));
}

__device__ __forceinline__ void ldm_x4(uint32_t addr, uint32_t* r) {
    asm volatile("ldmatrix.sync.aligned.m8n8.x4.shared.b16 {%0,%1,%2,%3}, [%4];"
                 : "=r"(r[0]), "=r"(r[1]), "=r"(r[2]), "=r"(r[3]) : "r"(addr));
}

__device__ __forceinline__ void mma_bf16(float* d, const uint32_t* a, uint32_t b0, uint32_t b1) {
    asm volatile("mma.sync.aligned.m16n8k16.row.col.f32.bf16.bf16.f32 "
                 "{%0,%1,%2,%3}, {%4,%5,%6,%7}, {%8,%9}, {%0,%1,%2,%3};"
                 : "+f"(d[0]), "+f"(d[1]), "+f"(d[2]), "+f"(d[3])
                 : "r"(a[0]), "r"(a[1]), "r"(a[2]), "r"(a[3]), "r"(b0), "r"(b1));
}

// ---------------------------------------------------------------------------
// Kernel A: logits = x @ W^T, split-bf16 x3 products (~4e-6 logit noise)
// ---------------------------------------------------------------------------
__global__ void __launch_bounds__(512, 1) gate_gemm(const float* __restrict__ A,
                                                    const float* __restrict__ W,
                                                    float* __restrict__ Copt) {
    if (blockIdx.x == 0 && threadIdx.x == 0) g_flag_count = 0;
    float* C = Copt ? Copt : g_logits;
    extern __shared__ char smem[];
    const uint32_t sb = smem_u32(smem);

    const int tid  = threadIdx.x;
    const int lane = tid & 31;
    const int wid  = tid >> 5;
    const int bm   = blockIdx.x * BM;
    const int warpM = wid >> 2;
    const int warpN = wid & 3;

    const int arow = tid >> 2;
    const int acb  = (tid & 3) * 8;
    const int wrow = tid >> 1;
    const int wcb  = (tid & 1) * 16;

    const float* aG = A + (size_t)(bm + arow) * HID + acb;
    const float* wG = W + (size_t)wrow * HID + wcb;

    const uint32_t aS0 = sb + (uint32_t)(arow * ROWB + acb * 2);
    const uint32_t aS1 = aS0 + A_TERM_BYTES;
    const uint32_t wS0 = sb + W_BASE + (uint32_t)(wrow * ROWB + wcb * 2);
    const uint32_t wS1 = wS0 + W_TERM_BYTES;

    const int lr = lane & 15, lh = lane >> 4;
    const uint32_t aL0 = sb + (uint32_t)((warpM * 32 + lr) * ROWB + lh * 16);
    const uint32_t aL1 = aL0 + A_TERM_BYTES;
    const uint32_t wL0 = sb + W_BASE + (uint32_t)((warpN * 64 + lr) * ROWB + lh * 16);
    const uint32_t wL1 = wL0 + W_TERM_BYTES;

    float acc[2][8][4];
#pragma unroll
    for (int i = 0; i < 2; ++i)
#pragma unroll
        for (int j = 0; j < 8; ++j)
#pragma unroll
            for (int k = 0; k < 4; ++k) acc[i][j][k] = 0.0f;

    float4 pa0, pa1, pw0, pw1, pw2, pw3;

    pa0 = *reinterpret_cast<const float4*>(aG + 0);
    pa1 = *reinterpret_cast<const float4*>(aG + 4);
    pw0 = *reinterpret_cast<const float4*>(wG + 0);
    pw1 = *reinterpret_cast<const float4*>(wG + 4);
    pw2 = *reinterpret_cast<const float4*>(wG + 8);
    pw3 = *reinterpret_cast<const float4*>(wG + 12);
    cvt_store8(pa0, pa1, aS0, aS1);
    cvt_store8(pw0, pw1, wS0, wS1);
    cvt_store8(pw2, pw3, wS0 + 16, wS1 + 16);
    __syncthreads();

    for (int kt = 0; kt < NCH; ++kt) {
        const uint32_t bufoff = (uint32_t)(kt & 1) * BUF_BYTES;
        if (kt + 1 < NCH) {
            const int ko = (kt + 1) * KC;
            pa0 = *reinterpret_cast<const float4*>(aG + ko);
            pa1 = *reinterpret_cast<const float4*>(aG + ko + 4);
            pw0 = *reinterpret_cast<const float4*>(wG + ko);
            pw1 = *reinterpret_cast<const float4*>(wG + ko + 4);
            pw2 = *reinterpret_cast<const float4*>(wG + ko + 8);
            pw3 = *reinterpret_cast<const float4*>(wG + ko + 12);
        }

#pragma unroll
        for (int s = 0; s < 2; ++s) {
            uint32_t af[2][2][4];
#pragma unroll
            for (int mt = 0; mt < 2; ++mt) {
                ldm_x4(aL0 + bufoff + (uint32_t)(mt * 16 * ROWB + s * 32), af[0][mt]);
                ldm_x4(aL1 + bufoff + (uint32_t)(mt * 16 * ROWB + s * 32), af[1][mt]);
            }
#pragma unroll
            for (int np = 0; np < 4; ++np) {
                uint32_t bf0[4], bf1[4];
                ldm_x4(wL0 + bufoff + (uint32_t)(np * 16 * ROWB + s * 32), bf0);
                ldm_x4(wL1 + bufoff + (uint32_t)(np * 16 * ROWB + s * 32), bf1);
#pragma unroll
                for (int mt = 0; mt < 2; ++mt) {
                    mma_bf16(acc[mt][np * 2 + 0], af[0][mt], bf0[0], bf0[2]);
                    mma_bf16(acc[mt][np * 2 + 1], af[0][mt], bf0[1], bf0[3]);
                    mma_bf16(acc[mt][np * 2 + 0], af[0][mt], bf1[0], bf1[2]);
                    mma_bf16(acc[mt][np * 2 + 1], af[0][mt], bf1[1], bf1[3]);
                    mma_bf16(acc[mt][np * 2 + 0], af[1][mt], bf0[0], bf0[2]);
                    mma_bf16(acc[mt][np * 2 + 1], af[1][mt], bf0[1], bf0[3]);
                }
            }
        }

        if (kt + 1 < NCH) {
            const uint32_t nb = (uint32_t)((kt + 1) & 1) * BUF_BYTES;
            cvt_store8(pa0, pa1, aS0 + nb, aS1 + nb);
            cvt_store8(pw0, pw1, wS0 + nb, wS1 + nb);
            cvt_store8(pw2, pw3, wS0 + nb + 16, wS1 + nb + 16);
        }
        __syncthreads();
    }

#pragma unroll
    for (int mt = 0; mt < 2; ++mt) {
#pragma unroll
        for (int nt = 0; nt < 8; ++nt) {
            int row = bm + warpM * 32 + mt * 16 + (lane >> 2);
            int col = warpN * 64 + nt * 8 + (lane & 3) * 2;
            float2 v0 = make_float2(acc[mt][nt][0], acc[mt][nt][1]);
            float2 v1 = make_float2(acc[mt][nt][2], acc[mt][nt][3]);
            *reinterpret_cast<float2*>(C + (size_t)row * N_EXP + col)       = v0;
            *reinterpret_cast<float2*>(C + (size_t)(row + 8) * N_EXP + col) = v1;
        }
    }
}

// ---------------------------------------------------------------------------
// Shared routing logic. FLAG=true: also compute decision margins and append
// ambiguous tokens to g_flag_list.
// ---------------------------------------------------------------------------
template <bool FLAG>
__device__ __forceinline__ void route_token(const float* row, const float* __restrict__ bias,
                                            int tok, int lane,
                                            float* idx_out, float* wt_out) {
    float s[8], sr[8];
#pragma unroll
    for (int i = 0; i < 8; ++i) {
        float x = row[lane * 8 + i];
        float sc = 1.0f / (1.0f + expf(-x));
        s[i]  = sc;
        sr[i] = sc + bias[lane * 8 + i];
    }

    float m1 = -INFINITY, m2 = -INFINITY;
#pragma unroll
    for (int i = 0; i < 8; ++i) {
        if (sr[i] > m1) { m2 = m1; m1 = sr[i]; }
        else if (sr[i] > m2) { m2 = sr[i]; }
    }
#pragma unroll
    for (int off = 1; off <= 2; off <<= 1) {
        float o1 = __shfl_xor_sync(0xffffffffu, m1, off);
        float o2 = __shfl_xor_sync(0xffffffffu, m2, off);
        if (o1 > m1) { m2 = fmaxf(m1, o2); m1 = o1; }
        else         { m2 = fmaxf(m2, o1); }
    }
    float gsum = m1 + m2;

    float gs[8];
#pragma unroll
    for (int g = 0; g < 8; ++g) gs[g] = __shfl_sync(0xffffffffu, gsum, g * 4);

    int myg = lane >> 2;
    int myrank = 0;
    float gmin_sel = INFINITY, gmax_uns = -INFINITY;
#pragma unroll
    for (int g = 0; g < 8; ++g) {
        int rk = 0;
#pragma unroll
        for (int h = 0; h < 8; ++h)
            rk += (gs[h] > gs[g]) || (gs[h] == gs[g] && h < g);
        if (g == myg) myrank = rk;
        if (FLAG) {
            if (rk < 4) gmin_sel = fminf(gmin_sel, gs[g]);
            else        gmax_uns = fmaxf(gmax_uns, gs[g]);
        }
    }
    bool group_sel = myrank < 4;

    float ms[8];
#pragma unroll
    for (int i = 0; i < 8; ++i) ms[i] = group_sel ? sr[i] : -INFINITY;

    bool used[8] = {false, false, false, false, false, false, false, false};
    int   sel_idx[8];
    float sel_s[8];
    float sel_r[8];
    float wsum = 0.0f;
    for (int k = 0; k < 8; ++k) {
        float bv = -INFINITY; int bi = 0x7fffffff;
#pragma unroll
        for (int i = 0; i < 8; ++i) {
            if (!used[i] && ms[i] > bv) { bv = ms[i]; bi = lane * 8 + i; }
        }
#pragma unroll
        for (int off = 16; off >= 1; off >>= 1) {
            float ov = __shfl_xor_sync(0xffffffffu, bv, off);
            int   oi = __shfl_xor_sync(0xffffffffu, bi, off);
            if (ov > bv || (ov == bv && oi < bi)) { bv = ov; bi = oi; }
        }
        int src = bi >> 3, slot = bi & 7;
        if (lane == src) used[slot] = true;
        float sc = 0.0f;
#pragma unroll
        for (int j = 0; j < 8; ++j)
            if (j == slot) sc = s[j];
        sc = __shfl_sync(0xffffffffu, sc, src);
        sel_idx[k] = bi;
        sel_s[k]   = sc;
        sel_r[k]   = bv;
        wsum += sc;
    }

    if (FLAG) {
        float bv9 = -INFINITY;
#pragma unroll
        for (int i = 0; i < 8; ++i)
            if (!used[i] && ms[i] > bv9) bv9 = ms[i];
#pragma unroll
        for (int off = 16; off >= 1; off >>= 1)
            bv9 = fmaxf(bv9, __shfl_xor_sync(0xffffffffu, bv9, off));

        bool flag = (gmin_sel - gmax_uns < DELTA) || (sel_r[7] - bv9 < DELTA);
#pragma unroll
        for (int k = 1; k < 8; ++k)
            flag = flag || (sel_r[k - 1] - sel_r[k] < DELTA);
        if (flag && lane == 0) {
            int p = atomicAdd(&g_flag_count, 1);
            g_flag_list[p] = tok;
        }
    }

    float scale = 2.5f / (wsum + 1e-20f);
    if (lane == 0) {
#pragma unroll
        for (int k = 0; k < 8; ++k) {
            idx_out[(size_t)tok * 8 + k] = (float)sel_idx[k];
            wt_out [(size_t)tok * 8 + k] = sel_s[k] * scale;
        }
    }
}

// ---------------------------------------------------------------------------
// Kernel B: provisional routing on noisy logits + ambiguity flagging
// ---------------------------------------------------------------------------
__global__ void __launch_bounds__(128) routing_flag(const float* __restrict__ logits_opt,
                                                    const float* __restrict__ bias,
                                                    float* idx_opt, float* wt_opt) {
    const float* lg = logits_opt ? logits_opt : g_logits;
    float* idx_out = idx_opt ? idx_opt : g_small;
    float* wt_out  = wt_opt  ? wt_opt  : (g_small + (size_t)T_TOK * 8);

    int tok = (int)((blockIdx.x * blockDim.x + threadIdx.x) >> 5);
    int lane = threadIdx.x & 31;
    if (tok >= T_TOK) return;
    route_token<true>(lg + (size_t)tok * N_EXP, bias, tok, lane, idx_out, wt_out);
}

// ---------------------------------------------------------------------------
// Kernel C: exact fp32 recompute + re-route for flagged tokens
// block: 1024 threads, 8 tokens x 256 experts; thread = (tl in 0..3, e in 0..255)
// handles tokens tl and tl+4 of the block's 8.
// ---------------------------------------------------------------------------
#define RB_TOK 8
__global__ void __launch_bounds__(1024) refine_kernel(const float* __restrict__ A,
                                                      const float* __restrict__ W,
                                                      const float* __restrict__ bias,
                                                      float* lg_opt, float* idx_opt, float* wt_opt) {
    float* lg = lg_opt ? lg_opt : g_logits;
    float* idx_out = idx_opt ? idx_opt : g_small;
    float* wt_out  = wt_opt  ? wt_opt  : (g_small + (size_t)T_TOK * 8);

    __shared__ float xs[RB_TOK][512];
    __shared__ float lsm[RB_TOK][256];
    __shared__ int   toks[RB_TOK];

    int count = g_flag_count;
    int base = blockIdx.x * RB_TOK;
    if (base >= count) return;

    int tid = threadIdx.x;
    if (tid < RB_TOK) {
        int sl = base + tid;
        toks[tid] = g_flag_list[sl < count ? sl : (count - 1)];
    }
    __syncthreads();

    const int e  = tid & 255;
    const int tl = tid >> 8;  // 0..3
    float acc0 = 0.0f, acc1 = 0.0f;
    const float* wr = W + (size_t)e * HID;

    for (int c = 0; c < 8; ++c) {
        {
            int t = tid >> 7;             // 0..7
            int pos = (tid & 127) * 4;
            *reinterpret_cast<float4*>(&xs[t][pos]) =
                *reinterpret_cast<const float4*>(A + (size_t)toks[t] * HID + c * 512 + pos);
        }
        __syncthreads();
        const float4* w4 = reinterpret_cast<const float4*>(wr + c * 512);
#pragma unroll 4
        for (int kk = 0; kk < 128; ++kk) {
            float4 wv = w4[kk];
            float4 x0 = *reinterpret_cast<const float4*>(&xs[tl][kk * 4]);
            float4 x1 = *reinterpret_cast<const float4*>(&xs[tl + 4][kk * 4]);
            acc0 += x0.x * wv.x; acc0 += x0.y * wv.y; acc0 += x0.z * wv.z; acc0 += x0.w * wv.w;
            acc1 += x1.x * wv.x; acc1 += x1.y * wv.y; acc1 += x1.z * wv.z; acc1 += x1.w * wv.w;
        }
        __syncthreads();
    }

    lsm[tl][e]     = acc0;
    lsm[tl + 4][e] = acc1;
    if (base + tl < count)     lg[(size_t)toks[tl] * N_EXP + e]     = acc0;
    if (base + tl + 4 < count) lg[(size_t)toks[tl + 4] * N_EXP + e] = acc1;
    __syncthreads();

    int wid = tid >> 5, lane = tid & 31;
    if (wid < RB_TOK && base + wid < count) {
        route_token<false>(&lsm[wid][0], bias, toks[wid], lane, idx_out, wt_out);
    }
}

// ---------------------------------------------------------------------------
extern "C" void kernel_launch(void* const* d_in, const int* in_sizes, int n_in,
                              void* d_out, int out_size) {
    const float* x    = (const float*)d_in[0];
    const float* w    = (const float*)d_in[1];
    const float* bias = (const float*)d_in[2];
    float* out = (float*)d_out;

    const long long TE  = (long long)T_TOK * N_EXP;
    const long long TK2 = (long long)T_TOK * 16;
    const long long TK  = (long long)T_TOK * 8;
    long long os = out_size;

    float *idxp = nullptr, *wtp = nullptr, *lgp = nullptr;
    if (os >= TK2 + TE) {
        idxp = out; wtp = out + TK; lgp = out + TK2;
    } else if (os == TE) {
        lgp = out;
    } else if (os == TK2) {
        idxp = out; wtp = out + TK;
    } else if (os == TK) {
        idxp = out;
    }

    cudaFuncSetAttribute(gate_gemm, cudaFuncAttributeMaxDynamicSharedMemorySize, SMEM_TOTAL);
    gate_gemm<<<T_TOK / BM, 512, SMEM_TOTAL>>>(x, w, lgp);
    routing_flag<<<T_TOK / 4, 128>>>(lgp, bias, idxp, wtp);
    refine_kernel<<<T_TOK / RB_TOK, 1024>>>(x, w, bias, lgp, idxp, wtp);
}